// round 9
// baseline (speedup 1.0000x reference)
#include <cuda_runtime.h>

// Inverse Haar (db1) 2D wavelet step, grouped transposed conv stride2/kernel2.
// Input  x: (16, 128, 128, 128) f32  -> channel pairs (2g, 2g+1)
// Filters:  (2, 2, 2) f32
// Output:   (16, 64, 256, 256) f32
//
// out[b,g,2h+i,2w+j] = x[b,2g,h,w]*f0[i,j] + x[b,2g+1,h,w]*f1[i,j]
//
// R8: persistent grid-stride version of the R5 warp-dense geometry.
// 592 CTAs (148 SMs x 4) x 512 threads loop over the 4,194,304 work items;
// the loop overlaps one iteration's stores with the next's loads and removes
// the ~14 CTA-wave boundaries of the one-shot launch. Memory layout per
// iteration is identical to R5 (measured optimum): loads 2x512B contiguous
// per warp per plane, stores 2KB fully contiguous per warp.

#define HW_IN   (128 * 128)
#define HW_OUT  (256 * 256)
#define W_IN    128
#define W_OUT   256

#define NBLOCKS 592
#define TPB     512
#define TOTAL   (16 * 64 * 128 * 32)   // 4,194,304 work items

__global__ __launch_bounds__(TPB) void iwt_kernel(
    const float* __restrict__ x,
    const float* __restrict__ f,
    float* __restrict__ out)
{
    const float f00 = __ldg(f + 0), f01 = __ldg(f + 1);
    const float f10 = __ldg(f + 2), f11 = __ldg(f + 3);
    const float g00 = __ldg(f + 4), g01 = __ldg(f + 5);
    const float g10 = __ldg(f + 6), g11 = __ldg(f + 7);

    const int stride = NBLOCKS * TPB;   // 303,104

    for (int tid = blockIdx.x * TPB + threadIdx.x; tid < TOTAL; tid += stride) {
        int i  = tid & 31;           // lane's float4-column slot
        int h  = (tid >> 5) & 127;   // input row
        int bg = tid >> 12;          // b*64 + g in [0,1024)

        // Input row bases: channel 2g at plane 2*bg, channel 2g+1 next plane.
        int in_base = 2 * bg * HW_IN + h * W_IN;
        const float2* arow = reinterpret_cast<const float2*>(x + in_base);
        const float2* brow = reinterpret_cast<const float2*>(x + in_base + HW_IN);

        // Four independent 8B loads, each 256B contiguous per warp.
        float2 aL = __ldg(arow + i);
        float2 bL = __ldg(brow + i);
        float2 aH = __ldg(arow + 32 + i);
        float2 bH = __ldg(brow + 32 + i);

        int out_base = bg * HW_OUT + (h << 1) * W_OUT;
        float4* orow0 = reinterpret_cast<float4*>(out + out_base);
        float4* orow1 = reinterpret_cast<float4*>(out + out_base + W_OUT);

        float4 r0L = make_float4(fmaf(bL.x, g00, aL.x * f00), fmaf(bL.x, g01, aL.x * f01),
                                 fmaf(bL.y, g00, aL.y * f00), fmaf(bL.y, g01, aL.y * f01));
        float4 r1L = make_float4(fmaf(bL.x, g10, aL.x * f10), fmaf(bL.x, g11, aL.x * f11),
                                 fmaf(bL.y, g10, aL.y * f10), fmaf(bL.y, g11, aL.y * f11));
        float4 r0H = make_float4(fmaf(bH.x, g00, aH.x * f00), fmaf(bH.x, g01, aH.x * f01),
                                 fmaf(bH.y, g00, aH.y * f00), fmaf(bH.y, g01, aH.y * f01));
        float4 r1H = make_float4(fmaf(bH.x, g10, aH.x * f10), fmaf(bH.x, g11, aH.x * f11),
                                 fmaf(bH.y, g10, aH.y * f10), fmaf(bH.y, g11, aH.y * f11));

        // Warp-dense streaming stores: the 4 STGs of a warp cover a
        // contiguous 2KB output block.
        __stcs(orow0 + i,      r0L);
        __stcs(orow0 + 32 + i, r0H);
        __stcs(orow1 + i,      r1L);
        __stcs(orow1 + 32 + i, r1H);
    }
}

extern "C" void kernel_launch(void* const* d_in, const int* in_sizes, int n_in,
                              void* d_out, int out_size) {
    const float* x = (const float*)d_in[0];   // (16,128,128,128) f32
    const float* f = (const float*)d_in[1];   // (2,2,2) f32
    float* out = (float*)d_out;               // (16,64,256,256) f32

    iwt_kernel<<<NBLOCKS, TPB>>>(x, f, out);
}

// round 11
// speedup vs baseline: 1.1404x; 1.1404x over previous
#include <cuda_runtime.h>

// Inverse Haar (db1) 2D wavelet step, grouped transposed conv stride2/kernel2.
// Input  x: (16, 128, 128, 128) f32  -> channel pairs (2g, 2g+1)
// Filters:  (2, 2, 2) f32
// Output:   (16, 64, 256, 256) f32
//
// out[b,g,2h+i,2w+j] = x[b,2g,h,w]*f0[i,j] + x[b,2g+1,h,w]*f1[i,j]
//
// FINAL (= R7, measured best 63.6us, DRAM 74.3% of spec / ~5.9 TB/s):
// one-shot launch, warp-dense geometry. Lane i loads input float2-cols
// {i, 32+i} of both channel planes (each LDG.64 = 256B contiguous/warp,
// MLP=4) and writes output float4-cols {i, 32+i} of rows 2h,2h+1 (each
// STG.128 = 512B contiguous/warp; a warp's 4 stores cover a contiguous
// 2KB block). Streaming store hint keeps the write-once output from
// thrashing L2. Verified terminal: R3 (dense-load corner), R6 (MLP=8),
// R8 (persistent grid) all matched or regressed vs this geometry while
// DRAM stayed pinned at ~74% -- the mixed-stream HBM ceiling.

#define HW_IN   (128 * 128)
#define HW_OUT  (256 * 256)
#define W_IN    128
#define W_OUT   256

__global__ __launch_bounds__(512) void iwt_kernel(
    const float* __restrict__ x,
    const float* __restrict__ f,
    float* __restrict__ out)
{
    int tid = blockIdx.x * blockDim.x + threadIdx.x;
    int i  = tid & 31;           // lane's float4-column slot
    int h  = (tid >> 5) & 127;   // input row
    int bg = tid >> 12;          // b*64 + g in [0,1024)

    const float f00 = __ldg(f + 0), f01 = __ldg(f + 1);
    const float f10 = __ldg(f + 2), f11 = __ldg(f + 3);
    const float g00 = __ldg(f + 4), g01 = __ldg(f + 5);
    const float g10 = __ldg(f + 6), g11 = __ldg(f + 7);

    // Input row bases: channel 2g at plane 2*bg, channel 2g+1 one plane later.
    int in_base = 2 * bg * HW_IN + h * W_IN;
    const float2* arow = reinterpret_cast<const float2*>(x + in_base);
    const float2* brow = reinterpret_cast<const float2*>(x + in_base + HW_IN);

    // Four independent 8B loads: input cols {2i,2i+1} and {64+2i,64+2i+1}.
    float2 aL = __ldg(arow + i);
    float2 bL = __ldg(brow + i);
    float2 aH = __ldg(arow + 32 + i);
    float2 bH = __ldg(brow + 32 + i);

    // Output rows 2h, 2h+1; thread writes float4-cols i (low) and 32+i (high).
    int out_base = bg * HW_OUT + (h << 1) * W_OUT;
    float4* orow0 = reinterpret_cast<float4*>(out + out_base);
    float4* orow1 = reinterpret_cast<float4*>(out + out_base + W_OUT);

    float4 r0L = make_float4(fmaf(bL.x, g00, aL.x * f00), fmaf(bL.x, g01, aL.x * f01),
                             fmaf(bL.y, g00, aL.y * f00), fmaf(bL.y, g01, aL.y * f01));
    float4 r1L = make_float4(fmaf(bL.x, g10, aL.x * f10), fmaf(bL.x, g11, aL.x * f11),
                             fmaf(bL.y, g10, aL.y * f10), fmaf(bL.y, g11, aL.y * f11));
    float4 r0H = make_float4(fmaf(bH.x, g00, aH.x * f00), fmaf(bH.x, g01, aH.x * f01),
                             fmaf(bH.y, g00, aH.y * f00), fmaf(bH.y, g01, aH.y * f01));
    float4 r1H = make_float4(fmaf(bH.x, g10, aH.x * f10), fmaf(bH.x, g11, aH.x * f11),
                             fmaf(bH.y, g10, aH.y * f10), fmaf(bH.y, g11, aH.y * f11));

    __stcs(orow0 + i,      r0L);
    __stcs(orow0 + 32 + i, r0H);
    __stcs(orow1 + i,      r1L);
    __stcs(orow1 + 32 + i, r1H);
}

extern "C" void kernel_launch(void* const* d_in, const int* in_sizes, int n_in,
                              void* d_out, int out_size) {
    const float* x = (const float*)d_in[0];   // (16,128,128,128) f32
    const float* f = (const float*)d_in[1];   // (2,2,2) f32
    float* out = (float*)d_out;               // (16,64,256,256) f32

    const int total = 16 * 64 * 128 * 32;     // 4,194,304 threads
    const int tpb = 512;
    iwt_kernel<<<total / tpb, tpb>>>(x, f, out);
}

// round 14
// speedup vs baseline: 1.1595x; 1.0167x over previous
#include <cuda_runtime.h>

// Inverse Haar (db1) 2D wavelet step, grouped transposed conv stride2/kernel2.
// Input  x: (16, 128, 128, 128) f32  -> channel pairs (2g, 2g+1)
// Filters:  (2, 2, 2) f32
// Output:   (16, 64, 256, 256) f32
//
// out[b,g,2h+i,2w+j] = x[b,2g,h,w]*f0[i,j] + x[b,2g+1,h,w]*f1[i,j]
//
// R11: 256-bit stores (st.global.cs.v8.f32, sm_100+). Lane j loads input
// float4 cols 4j..4j+3 from both channel planes (LDG.128, 512B dense/warp)
// and stores output cols 8j..8j+7 of rows 2h and 2h+1 (STG.256 -- ONE store
// instruction per warp covers a full contiguous 1KB output row). Both the
// load and store streams are now simultaneously fully warp-dense, which the
// 128-bit-store geometry (R5/R7) could not achieve.

#define HW_IN   (128 * 128)
#define HW_OUT  (256 * 256)
#define W_IN    128
#define W_OUT   256

__device__ __forceinline__ void stg256_cs(float* p, const float* v) {
    asm volatile(
        "st.global.cs.v8.f32 [%0], {%1, %2, %3, %4, %5, %6, %7, %8};"
        :: "l"(p),
           "f"(v[0]), "f"(v[1]), "f"(v[2]), "f"(v[3]),
           "f"(v[4]), "f"(v[5]), "f"(v[6]), "f"(v[7])
        : "memory");
}

__global__ __launch_bounds__(512) void iwt_kernel(
    const float* __restrict__ x,
    const float* __restrict__ f,
    float* __restrict__ out)
{
    int tid = blockIdx.x * blockDim.x + threadIdx.x;
    int j  = tid & 31;           // lane: input float4-chunk / output float8-chunk
    int h  = (tid >> 5) & 127;   // input row
    int bg = tid >> 12;          // b*64 + g in [0,1024)

    const float f00 = __ldg(f + 0), f01 = __ldg(f + 1);
    const float f10 = __ldg(f + 2), f11 = __ldg(f + 3);
    const float g00 = __ldg(f + 4), g01 = __ldg(f + 5);
    const float g10 = __ldg(f + 6), g11 = __ldg(f + 7);

    // Input: channel 2g at plane 2*bg, channel 2g+1 one plane later.
    int in_base = 2 * bg * HW_IN + h * W_IN;
    const float4* arow = reinterpret_cast<const float4*>(x + in_base);
    const float4* brow = reinterpret_cast<const float4*>(x + in_base + HW_IN);

    // Two dense LDG.128: each 512B contiguous per warp.
    float4 a = __ldg(arow + j);   // input cols 4j..4j+3, channel 2g
    float4 b = __ldg(brow + j);   // input cols 4j..4j+3, channel 2g+1

    // Output rows 2h, 2h+1; lane j writes cols 8j..8j+7 of each.
    int out_base = bg * HW_OUT + (h << 1) * W_OUT + (j << 3);

    float o0[8], o1[8];
    // input col c -> output cols 2c (filter col 0) and 2c+1 (filter col 1)
    o0[0] = fmaf(b.x, g00, a.x * f00);  o0[1] = fmaf(b.x, g01, a.x * f01);
    o0[2] = fmaf(b.y, g00, a.y * f00);  o0[3] = fmaf(b.y, g01, a.y * f01);
    o0[4] = fmaf(b.z, g00, a.z * f00);  o0[5] = fmaf(b.z, g01, a.z * f01);
    o0[6] = fmaf(b.w, g00, a.w * f00);  o0[7] = fmaf(b.w, g01, a.w * f01);

    o1[0] = fmaf(b.x, g10, a.x * f10);  o1[1] = fmaf(b.x, g11, a.x * f11);
    o1[2] = fmaf(b.y, g10, a.y * f10);  o1[3] = fmaf(b.y, g11, a.y * f11);
    o1[4] = fmaf(b.z, g10, a.z * f10);  o1[5] = fmaf(b.z, g11, a.z * f11);
    o1[6] = fmaf(b.w, g10, a.w * f10);  o1[7] = fmaf(b.w, g11, a.w * f11);

    // Two STG.256: each instruction = 1024B contiguous per warp (a full
    // 256-float output row).
    stg256_cs(out + out_base,         o0);
    stg256_cs(out + out_base + W_OUT, o1);
}

extern "C" void kernel_launch(void* const* d_in, const int* in_sizes, int n_in,
                              void* d_out, int out_size) {
    const float* x = (const float*)d_in[0];   // (16,128,128,128) f32
    const float* f = (const float*)d_in[1];   // (2,2,2) f32
    float* out = (float*)d_out;               // (16,64,256,256) f32

    const int total = 16 * 64 * 128 * 32;     // 4,194,304 threads
    const int tpb = 512;
    iwt_kernel<<<total / tpb, tpb>>>(x, f, out);
}